// round 8
// baseline (speedup 1.0000x reference)
#include <cuda_runtime.h>

// FoRefLoss: sum over B rows of (dx^2 + dy^2 + wrapped_angle^2), B=8388608.
// Champion codegen (grid-stride, 256 thr, `#pragma unroll 2`, dynamic mod-3
// masks, coalesced float4 loads) at EXACT full residency: 1184 CTAs = 8
// CTAs/SM on all 148 SMs (uniform wave, no ragged tail of light SMs).
// stride = 1184*256 = 303104 ≡ 2 (mod 3) -> m decrements each iteration.
// Angle term in turn-space: t = 2*min(frac(|d|), 1-frac(|d|)), contribution t^2.
// Single kernel; last-arriving block reduces partials in fixed order
// (deterministic: summation order independent of block arrival timing).

#define NBLOCKS 1184
#define NTHREADS 256

__device__ float g_partials[NBLOCKS];
__device__ unsigned int g_arrived = 0;

__device__ __forceinline__ float vcomp(float p, float l, bool is_angle) {
    float d = p - l;              // difference in "turns" (full circle = 1.0)
    float ad = fabsf(d);
    float f = ad - floorf(ad);    // frac in [0,1)
    float w = fminf(f, 1.0f - f); // folded to [0, 0.5]
    return is_angle ? (w + w) : d; // angle: 2w = clamped_angle/pi; else diff
}

__global__ void __launch_bounds__(NTHREADS)
foref_loss_kernel(const float4* __restrict__ pred,
                  const float4* __restrict__ lab,
                  int n4,                 // total float4 count per tensor
                  float* __restrict__ out)
{
    const int stride = NBLOCKS * NTHREADS;      // 303104; 303104 % 3 == 2
    int tid0 = blockIdx.x * NTHREADS + threadIdx.x;

    float sum = 0.0f;
    int iters = n4 / stride;   // 20 for n4 = 6291456 (leftover 229376 < stride)

    int k = tid0;
    int m = k % 3;

    #pragma unroll 2
    for (int it = 0; it < iters; ++it) {
        float4 p = pred[k];
        float4 l = lab[k];
        // component c is angle iff (k + c) % 3 == 2
        bool aA = (m == 2);   // c = 0 and c = 3
        bool aB = (m == 1);   // c = 1
        bool aC = (m == 0);   // c = 2
        float v;
        v = vcomp(p.x, l.x, aA); sum = fmaf(v, v, sum);
        v = vcomp(p.y, l.y, aB); sum = fmaf(v, v, sum);
        v = vcomp(p.z, l.z, aC); sum = fmaf(v, v, sum);
        v = vcomp(p.w, l.w, aA); sum = fmaf(v, v, sum);
        k += stride;
        m = (m >= 1) ? (m - 1) : 2;   // stride % 3 == 2  ->  m -= 1 (mod 3)
    }
    // tail: leftover n4 - iters*stride < stride, so at most one extra per thread
    if (k < n4) {
        float4 p = pred[k];
        float4 l = lab[k];
        bool aA = (m == 2), aB = (m == 1), aC = (m == 0);
        float v;
        v = vcomp(p.x, l.x, aA); sum = fmaf(v, v, sum);
        v = vcomp(p.y, l.y, aB); sum = fmaf(v, v, sum);
        v = vcomp(p.z, l.z, aC); sum = fmaf(v, v, sum);
        v = vcomp(p.w, l.w, aA); sum = fmaf(v, v, sum);
    }

    // intra-block reduce
    #pragma unroll
    for (int off = 16; off > 0; off >>= 1)
        sum += __shfl_down_sync(0xFFFFFFFFu, sum, off);

    __shared__ float smem[NTHREADS / 32];
    __shared__ bool is_last;
    int lane = threadIdx.x & 31;
    int wid  = threadIdx.x >> 5;
    if (lane == 0) smem[wid] = sum;
    __syncthreads();

    if (wid == 0) {
        float v = (lane < NTHREADS / 32) ? smem[lane] : 0.0f;
        #pragma unroll
        for (int off = 4; off > 0; off >>= 1)
            v += __shfl_down_sync(0xFFFFFFFFu, v, off);
        if (lane == 0) {
            g_partials[blockIdx.x] = v;
            __threadfence();
            unsigned int t = atomicAdd(&g_arrived, 1u);
            is_last = (t == (unsigned int)(gridDim.x - 1));
        }
    }
    __syncthreads();

    if (is_last) {
        // all partials are globally visible now; reduce in fixed order
        float v = 0.0f;
        for (int i = threadIdx.x; i < NBLOCKS; i += NTHREADS)
            v += g_partials[i];

        #pragma unroll
        for (int off = 16; off > 0; off >>= 1)
            v += __shfl_down_sync(0xFFFFFFFFu, v, off);

        if (lane == 0) smem[wid] = v;
        __syncthreads();

        if (wid == 0) {
            float t2 = (lane < NTHREADS / 32) ? smem[lane] : 0.0f;
            #pragma unroll
            for (int off = 4; off > 0; off >>= 1)
                t2 += __shfl_down_sync(0xFFFFFFFFu, t2, off);
            if (lane == 0) {
                out[0] = t2;
                g_arrived = 0;  // reset for next graph replay
            }
        }
    }
}

extern "C" void kernel_launch(void* const* d_in, const int* in_sizes, int n_in,
                              void* d_out, int out_size)
{
    const float4* pred = (const float4*)d_in[0];
    const float4* lab  = (const float4*)d_in[1];
    float* out = (float*)d_out;

    int n_floats = in_sizes[0];   // 25165824
    int n4 = n_floats / 4;        // 6291456

    foref_loss_kernel<<<NBLOCKS, NTHREADS>>>(pred, lab, n4, out);
}

// round 9
// speedup vs baseline: 1.0073x; 1.0073x over previous
#include <cuda_runtime.h>

// FoRefLoss: sum over B rows of (dx^2 + dy^2 + wrapped_angle^2), B=8388608.
// FINAL champion configuration (best of 8-round experiment matrix, reproduced
// twice at 35.33us total / 33.86us kernel, DRAM 76.7% = empirical HBM ceiling
// for this two-stream read pattern):
//   - coalesced float4 grid-stride loop, 1024 CTAs x 256 threads
//   - compiler-scheduled `#pragma unroll 2`, dynamic per-iteration mod-3
//     angle masks (every manual-scheduling variant regressed)
//   - angle term in turn-space: t = 2*min(frac(|d|), 1-frac(|d|)), term t^2
//     (identical to clamp(|d*2pi| mod 2pi)/pi, no fmod/constants needed)
//   - single kernel: last-arriving block reduces the 1024 partials in fixed
//     order (deterministic across replays) and resets the arrival counter.

#define NBLOCKS 1024
#define NTHREADS 256

__device__ float g_partials[NBLOCKS];
__device__ unsigned int g_arrived = 0;

__device__ __forceinline__ float vcomp(float p, float l, bool is_angle) {
    float d = p - l;              // difference in "turns" (full circle = 1.0)
    float ad = fabsf(d);
    float f = ad - floorf(ad);    // frac in [0,1)
    float w = fminf(f, 1.0f - f); // folded to [0, 0.5]
    return is_angle ? (w + w) : d; // angle: 2w = clamped_angle/pi; else diff
}

__global__ void __launch_bounds__(NTHREADS)
foref_loss_kernel(const float4* __restrict__ pred,
                  const float4* __restrict__ lab,
                  int n4,                 // total float4 count per tensor
                  float* __restrict__ out)
{
    const int stride = NBLOCKS * NTHREADS;      // 262144; 262144 % 3 == 1
    int tid0 = blockIdx.x * NTHREADS + threadIdx.x;

    float sum = 0.0f;
    int iters = n4 / stride;   // 24 exactly for n4 = 6291456

    int k = tid0;
    int m = k % 3;

    #pragma unroll 2
    for (int it = 0; it < iters; ++it) {
        float4 p = pred[k];
        float4 l = lab[k];
        // component c is angle iff (k + c) % 3 == 2
        bool aA = (m == 2);   // c = 0 and c = 3
        bool aB = (m == 1);   // c = 1
        bool aC = (m == 0);   // c = 2
        float v;
        v = vcomp(p.x, l.x, aA); sum = fmaf(v, v, sum);
        v = vcomp(p.y, l.y, aB); sum = fmaf(v, v, sum);
        v = vcomp(p.z, l.z, aC); sum = fmaf(v, v, sum);
        v = vcomp(p.w, l.w, aA); sum = fmaf(v, v, sum);
        k += stride;
        m = (m == 2) ? 0 : (m + 1);   // stride % 3 == 1
    }
    // generic tail (empty for n4 = 6291456)
    if (k < n4) {
        float4 p = pred[k];
        float4 l = lab[k];
        bool aA = (m == 2), aB = (m == 1), aC = (m == 0);
        float v;
        v = vcomp(p.x, l.x, aA); sum = fmaf(v, v, sum);
        v = vcomp(p.y, l.y, aB); sum = fmaf(v, v, sum);
        v = vcomp(p.z, l.z, aC); sum = fmaf(v, v, sum);
        v = vcomp(p.w, l.w, aA); sum = fmaf(v, v, sum);
    }

    // intra-block reduce
    #pragma unroll
    for (int off = 16; off > 0; off >>= 1)
        sum += __shfl_down_sync(0xFFFFFFFFu, sum, off);

    __shared__ float smem[NTHREADS / 32];
    __shared__ bool is_last;
    int lane = threadIdx.x & 31;
    int wid  = threadIdx.x >> 5;
    if (lane == 0) smem[wid] = sum;
    __syncthreads();

    if (wid == 0) {
        float v = (lane < NTHREADS / 32) ? smem[lane] : 0.0f;
        #pragma unroll
        for (int off = 4; off > 0; off >>= 1)
            v += __shfl_down_sync(0xFFFFFFFFu, v, off);
        if (lane == 0) {
            g_partials[blockIdx.x] = v;
            __threadfence();
            unsigned int t = atomicAdd(&g_arrived, 1u);
            is_last = (t == (unsigned int)(gridDim.x - 1));
        }
    }
    __syncthreads();

    if (is_last) {
        // all partials are globally visible now; reduce in fixed order
        float v = 0.0f;
        for (int i = threadIdx.x; i < NBLOCKS; i += NTHREADS)
            v += g_partials[i];

        #pragma unroll
        for (int off = 16; off > 0; off >>= 1)
            v += __shfl_down_sync(0xFFFFFFFFu, v, off);

        if (lane == 0) smem[wid] = v;
        __syncthreads();

        if (wid == 0) {
            float t2 = (lane < NTHREADS / 32) ? smem[lane] : 0.0f;
            #pragma unroll
            for (int off = 4; off > 0; off >>= 1)
                t2 += __shfl_down_sync(0xFFFFFFFFu, t2, off);
            if (lane == 0) {
                out[0] = t2;
                g_arrived = 0;  // reset for next graph replay
            }
        }
    }
}

extern "C" void kernel_launch(void* const* d_in, const int* in_sizes, int n_in,
                              void* d_out, int out_size)
{
    const float4* pred = (const float4*)d_in[0];
    const float4* lab  = (const float4*)d_in[1];
    float* out = (float*)d_out;

    int n_floats = in_sizes[0];   // 25165824
    int n4 = n_floats / 4;        // 6291456

    foref_loss_kernel<<<NBLOCKS, NTHREADS>>>(pred, lab, n4, out);
}